// round 8
// baseline (speedup 1.0000x reference)
#include <cuda_runtime.h>
#include <math.h>

#define NB     256
#define NPB    65536
#define NBATCH 4
#define EPS    1e-10f
#define INV_N  (1.0f / 65536.0f)

// ---------- persistent scratch (zero-init at load; re-zeroed every call) ----------
// 2D slot-shifted joint: J4[b][i0][j0] = contributions of the 2x2 patch based
// at (i0,j0): {.x=(i0,j0) .y=(i0,j0+1) .z=(i0+1,j0) .w=(i0+1,j0+1)}.
__device__ float4 g_J4[NBATCH][NB][NB];        // 4 MB, 16B-aligned cells
__device__ float  g_h1[NBATCH * NB];
__device__ float  g_h2[NBATCH * NB];
__device__ double g_sj[NBATCH];
__device__ double g_ej[NBATCH];
__device__ float  g_H1[NBATCH], g_H2[NBATCH];
__device__ unsigned g_bar1;

__device__ __forceinline__ void red4(float4* p, float a, float b, float c, float d) {
    asm volatile("red.global.add.v4.f32 [%0], {%1, %2, %3, %4};"
                 :: "l"(p), "f"(a), "f"(b), "f"(c), "f"(d) : "memory");
}

// ================= kernel 1: sparse KDE accumulation =================
// sigma=0.1 in bin units: only the two straddling bins carry weight (third
// bin <= e^-50 ~ 2e-22 relative). Joint: ONE aligned red.v4 per pixel.
// Marginals: shared-memory atomics.
#define THREADS_ACC 256
#define PIX_PER_CTA 1024

__global__ __launch_bounds__(THREADS_ACC)
void mi_accum_kernel(const float* __restrict__ in1, const float* __restrict__ in2) {
    __shared__ float sh1[NB];
    __shared__ float sh2[NB];
    int tid = threadIdx.x;
    int base = blockIdx.x * PIX_PER_CTA;
    int b = base >> 16;

    float4 a = ((const float4*)(in1 + base))[tid];
    float4 c = ((const float4*)(in2 + base))[tid];

    sh1[tid] = 0.0f;
    sh2[tid] = 0.0f;
    __syncthreads();

    const float xs1[4] = {a.x, a.y, a.z, a.w};
    const float xs2[4] = {c.x, c.y, c.z, c.w};

#pragma unroll
    for (int k = 0; k < 4; k++) {
        float x1 = xs1[k] * 255.0f;
        float x2 = xs2[k] * 255.0f;
        int i0 = min((int)floorf(x1), NB - 2);
        int j0 = min((int)floorf(x2), NB - 2);
        float f1 = x1 - (float)i0, q1 = 1.0f - f1;
        float f2 = x2 - (float)j0, q2 = 1.0f - f2;
        float wa1 = __expf(-50.0f * f1 * f1);
        float wb1 = __expf(-50.0f * q1 * q1);
        float wa2 = __expf(-50.0f * f2 * f2);
        float wb2 = __expf(-50.0f * q2 * q2);

        red4(&g_J4[b][i0][j0], wa1 * wa2, wa1 * wb2, wb1 * wa2, wb1 * wb2);

        atomicAdd(&sh1[i0],     wa1);
        atomicAdd(&sh1[i0 + 1], wb1);
        atomicAdd(&sh2[j0],     wa2);
        atomicAdd(&sh2[j0 + 1], wb2);
    }

    __syncthreads();
    atomicAdd(&g_h1[b * NB + tid], sh1[tid]);
    atomicAdd(&g_h2[b * NB + tid], sh2[tid]);
}

// ================= kernel 2: fold + reduce + combine + re-zero =================
__device__ __forceinline__ float fred256(float v, float* sred) {
#pragma unroll
    for (int o = 16; o; o >>= 1) v += __shfl_xor_sync(0xffffffffu, v, o);
    int wid = threadIdx.x >> 5, lid = threadIdx.x & 31;
    if (lid == 0) sred[wid] = v;
    __syncthreads();
    float rr = 0.0f;
    if (threadIdx.x < 32) {
        rr = (threadIdx.x < 8) ? sred[threadIdx.x] : 0.0f;
#pragma unroll
        for (int o = 4; o; o >>= 1) rr += __shfl_xor_sync(0xffffffffu, rr, o);
        if (threadIdx.x == 0) sred[0] = rr;
    }
    __syncthreads();
    float out = sred[0];
    __syncthreads();
    return out;
}

// 256 CTAs x 256 thr. CTA (rb, sub) computes cell rows [4sub..4sub+3].
// cell(r,j) = A[j].x + A[j-1].y + B[j].z + B[j-1].w  (A=base row r, B=row r-1).
// Zero policy: the .xy half of base row r is read ONLY by cell-row-r's CTA;
// the .zw half ONLY by cell-row-(r+1)'s CTA. Each thread zeroes exactly the
// float2 halves it read, after __syncthreads -> no cross-CTA races.
__global__ __launch_bounds__(256)
void mi_reduce_final_kernel(float* __restrict__ out) {
    __shared__ float sred[8];
    int tid = threadIdx.x;
    int rb  = blockIdx.x >> 6;
    int sub = blockIdx.x & 63;

    int row = 4 * sub + (tid >> 6);          // cell row r
    int c0  = (tid & 63) * 4;                // first cell j of this thread

    float4* Ap = &g_J4[rb][row][0];
    float4 A0 = Ap[c0], A1 = Ap[c0 + 1], A2 = Ap[c0 + 2], A3 = Ap[c0 + 3];
    float aprev = (c0 == 0) ? 0.0f : Ap[c0 - 1].y;

    float4 B0 = {0,0,0,0}, B1 = {0,0,0,0}, B2 = {0,0,0,0}, B3 = {0,0,0,0};
    float bprev = 0.0f;
    float4* Bp = &g_J4[rb][(row > 0) ? (row - 1) : 0][0];
    if (row > 0) {
        B0 = Bp[c0]; B1 = Bp[c0 + 1]; B2 = Bp[c0 + 2]; B3 = Bp[c0 + 3];
        bprev = (c0 == 0) ? 0.0f : Bp[c0 - 1].w;
    }

    __syncthreads();                          // all reads before any zeroing
    float2 z2 = make_float2(0.f, 0.f);
#pragma unroll
    for (int k = 0; k < 4; k++)
        ((float2*)(Ap + c0 + k))[0] = z2;     // zero .xy halves we read
    if (row > 0) {
#pragma unroll
        for (int k = 0; k < 4; k++)
            ((float2*)(Bp + c0 + k))[1] = z2; // zero .zw halves we read
    }

    float v0 = (A0.x + aprev) + (B0.z + bprev);
    float v1 = (A1.x + A0.y) + (B1.z + B0.w);
    float v2 = (A2.x + A1.y) + (B2.z + B1.w);
    float v3 = (A3.x + A2.y) + (B3.z + B2.w);

    float sj = (v0 + v1) + (v2 + v3);
    float ej = v0 * __log2f(v0 + EPS)
             + v1 * __log2f(v1 + EPS)
             + v2 * __log2f(v2 + EPS)
             + v3 * __log2f(v3 + EPS);

    sj = fred256(sj, sred);
    ej = fred256(ej, sred);
    if (tid == 0) {
        atomicAdd(&g_sj[rb], (double)sj);
        atomicAdd(&g_ej[rb], (double)ej);
    }

    // marginals: exact reference math, one CTA per batch
    if (sub == 0) {
        float h1 = __ldcg(&g_h1[rb * NB + tid]);
        float h2 = __ldcg(&g_h2[rb * NB + tid]);
        g_h1[rb * NB + tid] = 0.0f;           // same-thread read-then-zero
        g_h2[rb * NB + tid] = 0.0f;
        float m1 = h1 * INV_N;
        float m2 = h2 * INV_N;
        float S1 = fred256(m1, sred);
        float S2 = fred256(m2, sred);
        float p1v = m1 / (S1 + EPS);
        float p2v = m2 / (S2 + EPS);
        float e1 = fred256(p1v * __log2f(p1v + EPS), sred);
        float e2 = fred256(p2v * __log2f(p2v + EPS), sred);
        if (tid == 0) { g_H1[rb] = -e1; g_H2[rb] = -e2; }
    }

    // last-block combine + reset
    __threadfence();
    __syncthreads();
    if (tid == 0) {
        unsigned t = atomicAdd(&g_bar1, 1u);
        if (t == 255u) {
            __threadfence();
            double acc = 0.0;
#pragma unroll
            for (int bb = 0; bb < NBATCH; bb++) {
                double Sj = g_sj[bb];
                double Ej = g_ej[bb];
                double den = Sj + (double)EPS;
                // Hj = -sum q*log2(q+eps), q=j/(Sj+eps), factored single-pass
                double Hj = -(Ej - Sj * log2(den)) / den;
                double H1 = (double)g_H1[bb];
                double H2 = (double)g_H2[bb];
                acc += 2.0 * (H1 + H2 - Hj) / (H1 + H2);
                g_sj[bb] = 0.0; g_ej[bb] = 0.0;
                g_H1[bb] = 0.0f; g_H2[bb] = 0.0f;
            }
            out[0] = (float)(acc * 0.25);
            g_bar1 = 0u;
        }
    }
}

// ================= launch: 2 kernels =================
extern "C" void kernel_launch(void* const* d_in, const int* in_sizes, int n_in,
                              void* d_out, int out_size) {
    const float* in1 = (const float*)d_in[0];
    const float* in2 = (const float*)d_in[1];
    float* out = (float*)d_out;

    mi_accum_kernel<<<(NBATCH * NPB) / PIX_PER_CTA, THREADS_ACC>>>(in1, in2);
    mi_reduce_final_kernel<<<256, 256>>>(out);
}